// round 12
// baseline (speedup 1.0000x reference)
#include <cuda_runtime.h>
#include <cstdint>

// ---------------------------------------------------------------------------
// AttentionHead  B=8 S=4096 D=1024 DK=64
// Round 12: proj reverted to R10 skeleton (R11 split regressed) with two
// local fixes: (1) W pre-rounded once to tf32-exact g_Wr -> B-side CVTs gone;
// (2) k-slot relabel -> all fragment loads LDS.64 (stride 40, conflict-free).
// attn unchanged from R10 (validated 128 us).
// ---------------------------------------------------------------------------

constexpr int B  = 8;
constexpr int S  = 4096;
constexpr int D  = 1024;
constexpr int DK = 64;
constexpr int M  = B * S;

__device__ float g_Q[M * DK];
__device__ float g_K[M * DK];
__device__ float g_V[M * DK];    // used as [B][64][4096], t pair-permuted
__device__ float g_Wr[192 * D];  // tf32-exact [wQ|wK|wV], row-major [192][1024]

__device__ __forceinline__ float ex2f(float x) {
    float y; asm("ex2.approx.ftz.f32 %0, %1;" : "=f"(y) : "f"(x)); return y;
}
__device__ __forceinline__ uint32_t tf32_rna(float f) {
    uint32_t u; asm("cvt.rna.tf32.f32 %0, %1;" : "=r"(u) : "f"(f)); return u;
}
__device__ __forceinline__ float tf32ef(float f) {
    return __uint_as_float(tf32_rna(f));
}
__device__ __forceinline__ uint32_t f2u(float f) { return __float_as_uint(f); }

__host__ __device__ __forceinline__ int perm8(int u) {
    return 2 * (u & 3) + ((u >> 2) & 1);
}

__device__ __forceinline__ void cpa16(void* dst_smem, const void* src) {
    uint32_t a;
    asm("{ .reg .u64 t; cvta.to.shared.u64 t, %1; cvt.u32.u64 %0, t; }"
        : "=r"(a) : "l"(dst_smem));
    asm volatile("cp.async.cg.shared.global [%0], [%1], 16;" :: "r"(a), "l"(src));
}
#define CPA_COMMIT() asm volatile("cp.async.commit_group;" ::: "memory")
template <int N>
__device__ __forceinline__ void cpa_wait() {
    asm volatile("cp.async.wait_group %0;" :: "n"(N) : "memory");
}
#define BAR_SYNC(id) asm volatile("bar.sync %0, 256;" :: "r"(id) : "memory")

__device__ __forceinline__ void mma8(float c[4], const uint32_t a[4],
                                     uint32_t b0, uint32_t b1) {
    asm volatile(
        "mma.sync.aligned.m16n8k8.row.col.f32.tf32.tf32.f32 "
        "{%0,%1,%2,%3}, {%4,%5,%6,%7}, {%8,%9}, {%0,%1,%2,%3};"
        : "+f"(c[0]), "+f"(c[1]), "+f"(c[2]), "+f"(c[3])
        : "r"(a[0]), "r"(a[1]), "r"(a[2]), "r"(a[3]), "r"(b0), "r"(b1));
}

constexpr float NEG = -1e30f;

// ---------------------------------------------------------------------------
// Phase 0: round W once to tf32-exact fp32 (192x1024 = 196608 elems)
// ---------------------------------------------------------------------------
__global__ void w_round_kernel(const float* __restrict__ wq,
                               const float* __restrict__ wk,
                               const float* __restrict__ wv)
{
    int i = blockIdx.x * 256 + threadIdx.x;     // 768 blocks x 256 = 196608
    int n = i >> 10;
    const float* w = (n < 64) ? wq : (n < 128) ? wk : wv;
    g_Wr[i] = tf32ef(w[(size_t)(n & 63) * D + (i & 1023)]);
}

// ---------------------------------------------------------------------------
// Phase 1: C[M,192] = X[M,1024] @ Wr^T   (R10 skeleton, stride 40,
// k-relabeled LDS.64 fragments, B-side CVT-free)
// ---------------------------------------------------------------------------
constexpr int PSTR = 40;
constexpr int PXS  = 256 * PSTR;              // 10240 floats
constexpr int PWS  = 192 * PSTR;              // 7680 floats
constexpr int PSTG = PXS + PWS;               // 17920 floats
constexpr int PROJ_SMEM = 2 * PSTG * 4;       // 143360 B

__global__ __launch_bounds__(512, 1)
void proj_kernel(const float* __restrict__ x)
{
    extern __shared__ float ps[];
    const int tid  = threadIdx.x;
    const int lane = tid & 31;
    const int warp = tid >> 5;
    const int wm   = warp & 7;                // 8 M-groups of 32 rows
    const int wn   = warp >> 3;               // 2 N-groups of 96 cols
    const int p4   = lane >> 2;
    const int q4   = lane & 3;
    const int m0   = blockIdx.x * 256;

    auto load_stage = [&](int st, int k0) {
        float* xs = ps + st * PSTG;
        float* ws = xs + PXS;
#pragma unroll
        for (int p = 0; p < 4; p++) {         // x: 256 rows x 32 f = 2048 chunks
            int c = tid + p * 512;
            int t = c >> 3, seg = c & 7;
            cpa16(xs + t * PSTR + seg * 4, x + (size_t)(m0 + t) * D + k0 + seg * 4);
        }
#pragma unroll
        for (int p = 0; p < 3; p++) {         // Wr: 192 rows x 32 f = 1536 chunks
            int c = tid + p * 512;
            int n = c >> 3, seg = c & 7;
            cpa16(ws + n * PSTR + seg * 4, g_Wr + (size_t)n * D + k0 + seg * 4);
        }
        CPA_COMMIT();
    };

    float acc[2][12][4];
#pragma unroll
    for (int mt = 0; mt < 2; mt++)
#pragma unroll
        for (int nt = 0; nt < 12; nt++)
#pragma unroll
            for (int e = 0; e < 4; e++) acc[mt][nt][e] = 0.0f;

    load_stage(0, 0);

    for (int it = 0; it < 32; ++it) {
        cpa_wait<0>();
        __syncthreads();
        if (it + 1 < 32) load_stage((it + 1) & 1, (it + 1) * 32);

        const float* xs = ps + (it & 1) * PSTG;
        const float* ws = xs + PXS;
        // k-relabel: slot pair (q4, q4+4) <- positions (2q4, 2q4+1), both operands
        const float* aB = xs + (wm * 32 + p4) * PSTR + 2 * q4;
        const float* bB = ws + (wn * 96 + p4) * PSTR + 2 * q4;

#pragma unroll
        for (int s = 0; s < 4; s++) {
            uint32_t a[2][4];
#pragma unroll
            for (int mt = 0; mt < 2; mt++) {
                const float* ap = aB + mt * 16 * PSTR + s * 8;
                float2 lo = *(const float2*)ap;
                float2 hi = *(const float2*)(ap + 8 * PSTR);
                a[mt][0] = tf32_rna(lo.x);
                a[mt][1] = tf32_rna(hi.x);
                a[mt][2] = tf32_rna(lo.y);
                a[mt][3] = tf32_rna(hi.y);
            }
#pragma unroll
            for (int nt = 0; nt < 12; nt++) {
                float2 bv = *(const float2*)(bB + nt * 8 * PSTR + s * 8);
                mma8(acc[0][nt], a[0], f2u(bv.x), f2u(bv.y));
                mma8(acc[1][nt], a[1], f2u(bv.x), f2u(bv.y));
            }
        }
    }

    // epilogue: Q scaled; tf32-exact outputs; permuted scratch layouts.
    const float SC = (float)(1.4426950408889634 / 32.0);
#pragma unroll
    for (int mt = 0; mt < 2; mt++) {
#pragma unroll
        for (int nt = 0; nt < 12; nt++) {
            int col = wn * 96 + nt * 8 + 2 * q4;
            int row = m0 + wm * 32 + mt * 16 + p4;
            if (col < 128) {
                float* outp = (col < 64) ? g_Q : g_K;
                float sc = (col < 64) ? SC : 1.0f;
                int b8  = (col & 63) & ~7;
                int p0  = b8 | perm8(col & 7);
                int p1  = b8 | perm8((col + 1) & 7);
                outp[(size_t)row * DK + p0]       = tf32ef(acc[mt][nt][0] * sc);
                outp[(size_t)row * DK + p1]       = tf32ef(acc[mt][nt][1] * sc);
                outp[(size_t)(row + 8) * DK + p0] = tf32ef(acc[mt][nt][2] * sc);
                outp[(size_t)(row + 8) * DK + p1] = tf32ef(acc[mt][nt][3] * sc);
            } else {
                int lc = col & 63;
                int b0r = row >> 12,  s0 = row & 4095;
                int b1r = (row + 8) >> 12, s1 = (row + 8) & 4095;
                size_t pt0 = (size_t)(s0 & ~7) | perm8(s0 & 7);
                size_t pt1 = (size_t)(s1 & ~7) | perm8(s1 & 7);
                g_V[((size_t)b0r * 64 + lc)     * 4096 + pt0] = tf32ef(acc[mt][nt][0]);
                g_V[((size_t)b0r * 64 + lc + 1) * 4096 + pt0] = tf32ef(acc[mt][nt][1]);
                g_V[((size_t)b1r * 64 + lc)     * 4096 + pt1] = tf32ef(acc[mt][nt][2]);
                g_V[((size_t)b1r * 64 + lc + 1) * 4096 + pt1] = tf32ef(acc[mt][nt][3]);
            }
        }
    }
}

// ---------------------------------------------------------------------------
// Phase 2: flash attention (unchanged from R10).
// ---------------------------------------------------------------------------
constexpr int KSZ  = 128 * 72;
constexpr int VTSZ = 64 * 136;
constexpr int STG  = KSZ + VTSZ;
constexpr int COFF = 2 * STG;
constexpr int CSZ  = 128 * 132;
constexpr int ATTN_SMEM = (COFF + CSZ) * 4;   // 210944 B

__global__ __launch_bounds__(512, 1)
void attn_kernel(float* __restrict__ out)
{
    extern __shared__ float sm[];
    __shared__ float Xm[128];
    __shared__ float Xl[128];

    const int b    = blockIdx.y;
    const int pj   = blockIdx.x;
    const int tid  = threadIdx.x;
    const int lane = tid & 31;
    const int warp = tid >> 5;
    const int wc   = warp >> 3;
    const int wr   = warp & 7;
    const int wb   = wr * 16;
    const int kb   = wc * 64;
    const int p4   = lane >> 2;
    const int q4   = lane & 3;
    const int htid = tid & 255;
    const int barid = 1 + wc;

    float* Cs = sm + COFF;

    auto load_kv = [&](int kt, int st) {
        float* Ks  = sm + st * STG;
        float* VTs = Ks + KSZ;
        const int t0 = kt * 128;
#pragma unroll
        for (int p = 0; p < 4; p++) {
            int c = htid + p * 256;
            int tl = c >> 4, seg = c & 15;
            int slot = kb + ((tl & ~7) | perm8(tl & 7));
            cpa16(Ks + slot * 72 + seg * 4,
                  g_K + ((size_t)(b * S + t0 + kb + tl)) * 64 + seg * 4);
        }
#pragma unroll
        for (int p = 0; p < 4; p++) {
            int c = htid + p * 256;
            int dk = c >> 4, ch = c & 15;
            cpa16(VTs + dk * 136 + kb + ch * 4,
                  g_V + ((size_t)b * 64 + dk) * 4096 + t0 + kb + ch * 4);
        }
        CPA_COMMIT();
    };

    for (int qsel = 0; qsel < 2; qsel++) {
        const int qt = qsel ? (31 - pj) : pj;
        const int q0 = qt * 128;
        const int nt = qt + 1;

        load_kv(0, 0);

        uint32_t qa[8][4];
#pragma unroll
        for (int s = 0; s < 8; s++) {
            const float* qp = g_Q + ((size_t)(b * S + q0 + wb + p4)) * 64 + s * 8 + 2 * q4;
            float2 lo = *(const float2*)qp;
            float2 hi = *(const float2*)(qp + 8 * 64);
            qa[s][0] = f2u(lo.x);
            qa[s][1] = f2u(hi.x);
            qa[s][2] = f2u(lo.y);
            qa[s][3] = f2u(hi.y);
        }

        float of[8][4];
        float m0r = NEG, m1r = NEG, l0 = 0.0f, l1 = 0.0f;
#pragma unroll
        for (int j = 0; j < 8; j++)
#pragma unroll
            for (int e = 0; e < 4; e++) of[j][e] = 0.0f;

        for (int it = 0; it < nt; ++it) {
            const int st = it & 1;
            cpa_wait<0>();
            BAR_SYNC(barid);
            if (it + 1 < nt) load_kv(it + 1, st ^ 1);

            if (it == qt && kb > wb + 15) continue;

            const float* Ks  = sm + st * STG;
            const float* VTs = Ks + KSZ;

            float sf[8][4];
#pragma unroll
            for (int j = 0; j < 8; j++)
#pragma unroll
                for (int e = 0; e < 4; e++) sf[j][e] = 0.0f;

            const float* kB = Ks + (kb + p4) * 72 + 2 * q4;
#pragma unroll
            for (int s = 0; s < 8; s++) {
                const float* kp = kB + s * 8;
#pragma unroll
                for (int j = 0; j < 8; j++) {
                    float2 kv2 = *(const float2*)(kp + j * 8 * 72);
                    mma8(sf[j], qa[s], f2u(kv2.x), f2u(kv2.y));
                }
            }

            if (it == qt) {
                int r0 = wb + p4;
#pragma unroll
                for (int j = 0; j < 8; j++) {
                    int ta = kb + j * 8 + q4;
                    int tb = ta + 4;
                    if (ta > r0)     sf[j][0] = NEG;
                    if (tb > r0)     sf[j][1] = NEG;
                    if (ta > r0 + 8) sf[j][2] = NEG;
                    if (tb > r0 + 8) sf[j][3] = NEG;
                }
            }

            float mx0 = NEG, mx1 = NEG;
#pragma unroll
            for (int j = 0; j < 8; j++) {
                mx0 = fmaxf(mx0, fmaxf(sf[j][0], sf[j][1]));
                mx1 = fmaxf(mx1, fmaxf(sf[j][2], sf[j][3]));
            }
            mx0 = fmaxf(mx0, __shfl_xor_sync(0xffffffffu, mx0, 1));
            mx0 = fmaxf(mx0, __shfl_xor_sync(0xffffffffu, mx0, 2));
            mx1 = fmaxf(mx1, __shfl_xor_sync(0xffffffffu, mx1, 1));
            mx1 = fmaxf(mx1, __shfl_xor_sync(0xffffffffu, mx1, 2));
            float mn0 = fmaxf(m0r, mx0), mn1 = fmaxf(m1r, mx1);
            float al0 = ex2f(m0r - mn0), al1 = ex2f(m1r - mn1);
            float keep0 = (mn0 > -1e29f) ? 1.0f : 0.0f;
            float keep1 = (mn1 > -1e29f) ? 1.0f : 0.0f;
            m0r = mn0; m1r = mn1;
#pragma unroll
            for (int j = 0; j < 8; j++) {
                of[j][0] *= al0; of[j][1] *= al0;
                of[j][2] *= al1; of[j][3] *= al1;
            }

            float rs0 = 0.0f, rs1 = 0.0f;
            const float* vB = VTs + p4 * 136 + kb + 2 * q4;
#pragma unroll
            for (int s2 = 0; s2 < 8; s2++) {
                float p00 = tf32ef(ex2f(sf[s2][0] - mn0)) * keep0;
                float p01 = tf32ef(ex2f(sf[s2][1] - mn0)) * keep0;
                float p10 = tf32ef(ex2f(sf[s2][2] - mn1)) * keep1;
                float p11 = tf32ef(ex2f(sf[s2][3] - mn1)) * keep1;
                rs0 += p00 + p01;
                rs1 += p10 + p11;
                uint32_t pa[4];
                pa[0] = f2u(p00); pa[1] = f2u(p10);
                pa[2] = f2u(p01); pa[3] = f2u(p11);
                const float* vp = vB + s2 * 8;
#pragma unroll
                for (int j2 = 0; j2 < 8; j2++) {
                    float2 vv = *(const float2*)(vp + j2 * 8 * 136);
                    mma8(of[j2], pa, f2u(vv.x), f2u(vv.y));
                }
            }
            rs0 += __shfl_xor_sync(0xffffffffu, rs0, 1);
            rs0 += __shfl_xor_sync(0xffffffffu, rs0, 2);
            rs1 += __shfl_xor_sync(0xffffffffu, rs1, 1);
            rs1 += __shfl_xor_sync(0xffffffffu, rs1, 2);
            l0 = l0 * al0 + rs0;
            l1 = l1 * al1 + rs1;
        }

        __syncthreads();
        if (wc == 1) {
            float* cb = Cs + (wb + p4) * 132 + 2 * q4;
#pragma unroll
            for (int j2 = 0; j2 < 8; j2++) {
                *(float2*)(cb + j2 * 8)           = make_float2(of[j2][0], of[j2][1]);
                *(float2*)(cb + 8 * 132 + j2 * 8) = make_float2(of[j2][2], of[j2][3]);
            }
            if (q4 == 0) {
                Xm[wb + p4]     = m0r;  Xl[wb + p4]     = l0;
                Xm[wb + p4 + 8] = m1r;  Xl[wb + p4 + 8] = l1;
            }
        }
        __syncthreads();
        if (wc == 0) {
            float mo0 = Xm[wb + p4],     lo0 = Xl[wb + p4];
            float mo1 = Xm[wb + p4 + 8], lo1 = Xl[wb + p4 + 8];
            float mg0 = fmaxf(m0r, mo0), mg1 = fmaxf(m1r, mo1);
            float s0 = ex2f(m0r - mg0), t0 = ex2f(mo0 - mg0);
            float s1 = ex2f(m1r - mg1), t1 = ex2f(mo1 - mg1);
            float inv0 = 1.0f / (l0 * s0 + lo0 * t0);
            float inv1 = 1.0f / (l1 * s1 + lo1 * t1);
            const float* cb = Cs + (wb + p4) * 132 + 2 * q4;
            float* orow0 = out + ((size_t)(b * S + q0 + wb + p4)) * 64 + 2 * q4;
            float* orow1 = orow0 + 8 * 64;
#pragma unroll
            for (int j2 = 0; j2 < 8; j2++) {
                float2 c0 = *(const float2*)(cb + j2 * 8);
                float2 c1 = *(const float2*)(cb + 8 * 132 + j2 * 8);
                *(float2*)(orow0 + j2 * 8) =
                    make_float2((of[j2][0] * s0 + c0.x * t0) * inv0,
                                (of[j2][1] * s0 + c0.y * t0) * inv0);
                *(float2*)(orow1 + j2 * 8) =
                    make_float2((of[j2][2] * s1 + c1.x * t1) * inv1,
                                (of[j2][3] * s1 + c1.y * t1) * inv1);
            }
        }
        __syncthreads();
    }
}

// ---------------------------------------------------------------------------
extern "C" void kernel_launch(void* const* d_in, const int* in_sizes, int n_in,
                              void* d_out, int out_size)
{
    const float* x  = (const float*)d_in[0];
    const float* wq = (const float*)d_in[1];
    const float* wk = (const float*)d_in[2];
    const float* wv = (const float*)d_in[3];
    float* out = (float*)d_out;

    cudaFuncSetAttribute(proj_kernel,
                         cudaFuncAttributeMaxDynamicSharedMemorySize, PROJ_SMEM);
    cudaFuncSetAttribute(attn_kernel,
                         cudaFuncAttributeMaxDynamicSharedMemorySize, ATTN_SMEM);

    w_round_kernel<<<768, 256>>>(wq, wk, wv);
    proj_kernel<<<M / 256, 512, PROJ_SMEM>>>(x);
    attn_kernel<<<dim3(16, B), 512, ATTN_SMEM>>>(out);
}

// round 13
// speedup vs baseline: 1.0538x; 1.0538x over previous
#include <cuda_runtime.h>
#include <cstdint>

// ---------------------------------------------------------------------------
// AttentionHead  B=8 S=4096 D=1024 DK=64
// Round 13: proj reverted to R10 verbatim (R11/R12 k-relabel regressed it).
// attn: R10 body, but grid = 148 blocks with atomic work-stealing over 256
// (batch, q-tile) units in LPT order (qt descending) -> no idle SMs,
// makespan 33 -> ~29 tile-units. Counter reset by proj (stream-ordered).
// ---------------------------------------------------------------------------

constexpr int B  = 8;
constexpr int S  = 4096;
constexpr int D  = 1024;
constexpr int DK = 64;
constexpr int M  = B * S;

__device__ float g_Q[M * DK];
__device__ float g_K[M * DK];
__device__ float g_V[M * DK];   // used as [B][64][4096], t pair-permuted
__device__ int   g_ctr;         // attn work-steal counter (reset by proj)

__device__ __forceinline__ float ex2f(float x) {
    float y; asm("ex2.approx.ftz.f32 %0, %1;" : "=f"(y) : "f"(x)); return y;
}
__device__ __forceinline__ uint32_t tf32_rna(float f) {
    uint32_t u; asm("cvt.rna.tf32.f32 %0, %1;" : "=r"(u) : "f"(f)); return u;
}
__device__ __forceinline__ float tf32ef(float f) {
    return __uint_as_float(tf32_rna(f));
}
__device__ __forceinline__ uint32_t f2u(float f) { return __float_as_uint(f); }

__host__ __device__ __forceinline__ int perm8(int u) {
    return 2 * (u & 3) + ((u >> 2) & 1);
}

__device__ __forceinline__ void cpa16(void* dst_smem, const void* src) {
    uint32_t a;
    asm("{ .reg .u64 t; cvta.to.shared.u64 t, %1; cvt.u32.u64 %0, t; }"
        : "=r"(a) : "l"(dst_smem));
    asm volatile("cp.async.cg.shared.global [%0], [%1], 16;" :: "r"(a), "l"(src));
}
#define CPA_COMMIT() asm volatile("cp.async.commit_group;" ::: "memory")
template <int N>
__device__ __forceinline__ void cpa_wait() {
    asm volatile("cp.async.wait_group %0;" :: "n"(N) : "memory");
}
#define BAR_SYNC(id) asm volatile("bar.sync %0, 256;" :: "r"(id) : "memory")

__device__ __forceinline__ void mma8(float c[4], const uint32_t a[4],
                                     uint32_t b0, uint32_t b1) {
    asm volatile(
        "mma.sync.aligned.m16n8k8.row.col.f32.tf32.tf32.f32 "
        "{%0,%1,%2,%3}, {%4,%5,%6,%7}, {%8,%9}, {%0,%1,%2,%3};"
        : "+f"(c[0]), "+f"(c[1]), "+f"(c[2]), "+f"(c[3])
        : "r"(a[0]), "r"(a[1]), "r"(a[2]), "r"(a[3]), "r"(b0), "r"(b1));
}

constexpr float NEG = -1e30f;

// ---------------------------------------------------------------------------
// Phase 1: C[M,192] = X[M,1024] @ [wQ|wK|wV]^T  (R10 verbatim; + g_ctr reset)
// CTA 256x192, BK=32, 512 thr, stride 36, scalar LDS + per-use tf32 RNA.
// ---------------------------------------------------------------------------
constexpr int PXS = 256 * 36;
constexpr int PWS = 192 * 36;
constexpr int PSTG = PXS + PWS;
constexpr int PROJ_SMEM = 2 * PSTG * 4;       // 129024 B

__global__ __launch_bounds__(512, 1)
void proj_kernel(const float* __restrict__ x,
                 const float* __restrict__ wq,
                 const float* __restrict__ wk,
                 const float* __restrict__ wv)
{
    extern __shared__ float ps[];
    const int tid  = threadIdx.x;
    const int lane = tid & 31;
    const int warp = tid >> 5;
    const int wm   = warp & 7;
    const int wn   = warp >> 3;
    const int m0   = blockIdx.x * 256;

    if (blockIdx.x == 0 && tid == 0) g_ctr = 0;   // reset attn steal counter

    auto load_stage = [&](int st, int k0) {
        float* xs = ps + st * PSTG;
        float* ws = xs + PXS;
#pragma unroll
        for (int p = 0; p < 4; p++) {
            int c = tid + p * 512;
            int t = c >> 3, seg = c & 7;
            cpa16(xs + t * 36 + seg * 4, x + (size_t)(m0 + t) * D + k0 + seg * 4);
        }
#pragma unroll
        for (int p = 0; p < 3; p++) {
            int c = tid + p * 512;
            int n = c >> 3, seg = c & 7;
            const float* w = (n < 64) ? wq : (n < 128) ? wk : wv;
            cpa16(ws + n * 36 + seg * 4, w + (size_t)(n & 63) * D + k0 + seg * 4);
        }
        CPA_COMMIT();
    };

    float acc[2][12][4];
#pragma unroll
    for (int mt = 0; mt < 2; mt++)
#pragma unroll
        for (int nt = 0; nt < 12; nt++)
#pragma unroll
            for (int e = 0; e < 4; e++) acc[mt][nt][e] = 0.0f;

    load_stage(0, 0);

    for (int it = 0; it < 32; ++it) {
        cpa_wait<0>();
        __syncthreads();
        if (it + 1 < 32) load_stage((it + 1) & 1, (it + 1) * 32);

        const float* xs = ps + (it & 1) * PSTG;
        const float* ws = xs + PXS;
        const float* aB = xs + (wm * 32 + (lane >> 2)) * 36 + (lane & 3);
        const float* bB = ws + (wn * 96 + (lane >> 2)) * 36 + (lane & 3);

#pragma unroll
        for (int s = 0; s < 4; s++) {
            uint32_t a[2][4];
#pragma unroll
            for (int mt = 0; mt < 2; mt++) {
                const float* ap = aB + mt * 16 * 36 + s * 8;
                a[mt][0] = tf32_rna(ap[0]);
                a[mt][1] = tf32_rna(ap[8 * 36]);
                a[mt][2] = tf32_rna(ap[4]);
                a[mt][3] = tf32_rna(ap[8 * 36 + 4]);
            }
#pragma unroll
            for (int nt = 0; nt < 12; nt++) {
                const float* bp = bB + nt * 8 * 36 + s * 8;
                uint32_t b0 = tf32_rna(bp[0]);
                uint32_t b1 = tf32_rna(bp[4]);
                mma8(acc[0][nt], a[0], b0, b1);
                mma8(acc[1][nt], a[1], b0, b1);
            }
        }
    }

    // epilogue: Q scaled; all outputs tf32-exact; permuted scratch layouts.
    const float SC = (float)(1.4426950408889634 / 32.0);
#pragma unroll
    for (int mt = 0; mt < 2; mt++) {
#pragma unroll
        for (int nt = 0; nt < 12; nt++) {
            int col = wn * 96 + nt * 8 + 2 * (lane & 3);
            int row = m0 + wm * 32 + mt * 16 + (lane >> 2);
            if (col < 128) {
                float* outp = (col < 64) ? g_Q : g_K;
                float sc = (col < 64) ? SC : 1.0f;
                int b8  = (col & 63) & ~7;
                int p0  = b8 | perm8(col & 7);
                int p1  = b8 | perm8((col + 1) & 7);
                outp[(size_t)row * DK + p0]       = tf32ef(acc[mt][nt][0] * sc);
                outp[(size_t)row * DK + p1]       = tf32ef(acc[mt][nt][1] * sc);
                outp[(size_t)(row + 8) * DK + p0] = tf32ef(acc[mt][nt][2] * sc);
                outp[(size_t)(row + 8) * DK + p1] = tf32ef(acc[mt][nt][3] * sc);
            } else {
                int lc = col & 63;
                int b0r = row >> 12,  s0 = row & 4095;
                int b1r = (row + 8) >> 12, s1 = (row + 8) & 4095;
                size_t pt0 = (size_t)(s0 & ~7) | perm8(s0 & 7);
                size_t pt1 = (size_t)(s1 & ~7) | perm8(s1 & 7);
                g_V[((size_t)b0r * 64 + lc)     * 4096 + pt0] = tf32ef(acc[mt][nt][0]);
                g_V[((size_t)b0r * 64 + lc + 1) * 4096 + pt0] = tf32ef(acc[mt][nt][1]);
                g_V[((size_t)b1r * 64 + lc)     * 4096 + pt1] = tf32ef(acc[mt][nt][2]);
                g_V[((size_t)b1r * 64 + lc + 1) * 4096 + pt1] = tf32ef(acc[mt][nt][3]);
            }
        }
    }
}

// ---------------------------------------------------------------------------
// Phase 2: flash attention (R10 body) with work-stealing over 256 units.
// unit u -> qt = 31 - u/8 (LPT: longest first), batch = u%8.
// 148 blocks x 512 thr; de-lockstepped halves; register-resident P.
// ---------------------------------------------------------------------------
constexpr int KSZ  = 128 * 72;
constexpr int VTSZ = 64 * 136;
constexpr int STG  = KSZ + VTSZ;
constexpr int COFF = 2 * STG;
constexpr int CSZ  = 128 * 132;
constexpr int ATTN_SMEM = (COFF + CSZ) * 4;   // 210944 B
constexpr int N_UNITS = 256;

__global__ __launch_bounds__(512, 1)
void attn_kernel(float* __restrict__ out)
{
    extern __shared__ float sm[];
    __shared__ float Xm[128];
    __shared__ float Xl[128];
    __shared__ int   s_unit;

    const int tid  = threadIdx.x;
    const int lane = tid & 31;
    const int warp = tid >> 5;
    const int wc   = warp >> 3;
    const int wr   = warp & 7;
    const int wb   = wr * 16;
    const int kb   = wc * 64;
    const int p4   = lane >> 2;
    const int q4   = lane & 3;
    const int htid = tid & 255;
    const int barid = 1 + wc;

    float* Cs = sm + COFF;

    while (true) {
        if (tid == 0) s_unit = atomicAdd(&g_ctr, 1);
        __syncthreads();
        const int u = s_unit;
        if (u >= N_UNITS) break;
        const int qt = 31 - (u >> 3);         // LPT: longest q-tiles first
        const int b  = u & 7;
        const int q0 = qt * 128;
        const int nt = qt + 1;

        auto load_kv = [&](int kt, int st) {
            float* Ks  = sm + st * STG;
            float* VTs = Ks + KSZ;
            const int t0 = kt * 128;
#pragma unroll
            for (int p = 0; p < 4; p++) {
                int c = htid + p * 256;
                int tl = c >> 4, seg = c & 15;
                int slot = kb + ((tl & ~7) | perm8(tl & 7));
                cpa16(Ks + slot * 72 + seg * 4,
                      g_K + ((size_t)(b * S + t0 + kb + tl)) * 64 + seg * 4);
            }
#pragma unroll
            for (int p = 0; p < 4; p++) {
                int c = htid + p * 256;
                int dk = c >> 4, ch = c & 15;
                cpa16(VTs + dk * 136 + kb + ch * 4,
                      g_V + ((size_t)b * 64 + dk) * 4096 + t0 + kb + ch * 4);
            }
            CPA_COMMIT();
        };

        load_kv(0, 0);

        uint32_t qa[8][4];
#pragma unroll
        for (int s = 0; s < 8; s++) {
            const float* qp = g_Q + ((size_t)(b * S + q0 + wb + p4)) * 64 + s * 8 + 2 * q4;
            float2 lo = *(const float2*)qp;
            float2 hi = *(const float2*)(qp + 8 * 64);
            qa[s][0] = f2u(lo.x);
            qa[s][1] = f2u(hi.x);
            qa[s][2] = f2u(lo.y);
            qa[s][3] = f2u(hi.y);
        }

        float of[8][4];
        float m0r = NEG, m1r = NEG, l0 = 0.0f, l1 = 0.0f;
#pragma unroll
        for (int j = 0; j < 8; j++)
#pragma unroll
            for (int e = 0; e < 4; e++) of[j][e] = 0.0f;

        for (int it = 0; it < nt; ++it) {
            const int st = it & 1;
            cpa_wait<0>();
            BAR_SYNC(barid);
            if (it + 1 < nt) load_kv(it + 1, st ^ 1);

            if (it == qt && kb > wb + 15) continue;   // fully-masked quarter

            const float* Ks  = sm + st * STG;
            const float* VTs = Ks + KSZ;

            float sf[8][4];
#pragma unroll
            for (int j = 0; j < 8; j++)
#pragma unroll
                for (int e = 0; e < 4; e++) sf[j][e] = 0.0f;

            const float* kB = Ks + (kb + p4) * 72 + 2 * q4;
#pragma unroll
            for (int s = 0; s < 8; s++) {
                const float* kp = kB + s * 8;
#pragma unroll
                for (int j = 0; j < 8; j++) {
                    float2 kv2 = *(const float2*)(kp + j * 8 * 72);
                    mma8(sf[j], qa[s], f2u(kv2.x), f2u(kv2.y));
                }
            }

            if (it == qt) {
                int r0 = wb + p4;
#pragma unroll
                for (int j = 0; j < 8; j++) {
                    int ta = kb + j * 8 + q4;
                    int tb = ta + 4;
                    if (ta > r0)     sf[j][0] = NEG;
                    if (tb > r0)     sf[j][1] = NEG;
                    if (ta > r0 + 8) sf[j][2] = NEG;
                    if (tb > r0 + 8) sf[j][3] = NEG;
                }
            }

            float mx0 = NEG, mx1 = NEG;
#pragma unroll
            for (int j = 0; j < 8; j++) {
                mx0 = fmaxf(mx0, fmaxf(sf[j][0], sf[j][1]));
                mx1 = fmaxf(mx1, fmaxf(sf[j][2], sf[j][3]));
            }
            mx0 = fmaxf(mx0, __shfl_xor_sync(0xffffffffu, mx0, 1));
            mx0 = fmaxf(mx0, __shfl_xor_sync(0xffffffffu, mx0, 2));
            mx1 = fmaxf(mx1, __shfl_xor_sync(0xffffffffu, mx1, 1));
            mx1 = fmaxf(mx1, __shfl_xor_sync(0xffffffffu, mx1, 2));
            float mn0 = fmaxf(m0r, mx0), mn1 = fmaxf(m1r, mx1);
            float al0 = ex2f(m0r - mn0), al1 = ex2f(m1r - mn1);
            float keep0 = (mn0 > -1e29f) ? 1.0f : 0.0f;
            float keep1 = (mn1 > -1e29f) ? 1.0f : 0.0f;
            m0r = mn0; m1r = mn1;
#pragma unroll
            for (int j = 0; j < 8; j++) {
                of[j][0] *= al0; of[j][1] *= al0;
                of[j][2] *= al1; of[j][3] *= al1;
            }

            float rs0 = 0.0f, rs1 = 0.0f;
            const float* vB = VTs + p4 * 136 + kb + 2 * q4;
#pragma unroll
            for (int s2 = 0; s2 < 8; s2++) {
                float p00 = tf32ef(ex2f(sf[s2][0] - mn0)) * keep0;
                float p01 = tf32ef(ex2f(sf[s2][1] - mn0)) * keep0;
                float p10 = tf32ef(ex2f(sf[s2][2] - mn1)) * keep1;
                float p11 = tf32ef(ex2f(sf[s2][3] - mn1)) * keep1;
                rs0 += p00 + p01;
                rs1 += p10 + p11;
                uint32_t pa[4];
                pa[0] = f2u(p00); pa[1] = f2u(p10);
                pa[2] = f2u(p01); pa[3] = f2u(p11);
                const float* vp = vB + s2 * 8;
#pragma unroll
                for (int j2 = 0; j2 < 8; j2++) {
                    float2 vv = *(const float2*)(vp + j2 * 8 * 136);
                    mma8(of[j2], pa, f2u(vv.x), f2u(vv.y));
                }
            }
            rs0 += __shfl_xor_sync(0xffffffffu, rs0, 1);
            rs0 += __shfl_xor_sync(0xffffffffu, rs0, 2);
            rs1 += __shfl_xor_sync(0xffffffffu, rs1, 1);
            rs1 += __shfl_xor_sync(0xffffffffu, rs1, 2);
            l0 = l0 * al0 + rs0;
            l1 = l1 * al1 + rs1;
        }

        // ---- merge halves (exact LSE combine) ----
        __syncthreads();
        if (wc == 1) {
            float* cb = Cs + (wb + p4) * 132 + 2 * q4;
#pragma unroll
            for (int j2 = 0; j2 < 8; j2++) {
                *(float2*)(cb + j2 * 8)           = make_float2(of[j2][0], of[j2][1]);
                *(float2*)(cb + 8 * 132 + j2 * 8) = make_float2(of[j2][2], of[j2][3]);
            }
            if (q4 == 0) {
                Xm[wb + p4]     = m0r;  Xl[wb + p4]     = l0;
                Xm[wb + p4 + 8] = m1r;  Xl[wb + p4 + 8] = l1;
            }
        }
        __syncthreads();
        if (wc == 0) {
            float mo0 = Xm[wb + p4],     lo0 = Xl[wb + p4];
            float mo1 = Xm[wb + p4 + 8], lo1 = Xl[wb + p4 + 8];
            float mg0 = fmaxf(m0r, mo0), mg1 = fmaxf(m1r, mo1);
            float s0 = ex2f(m0r - mg0), t0 = ex2f(mo0 - mg0);
            float s1 = ex2f(m1r - mg1), t1 = ex2f(mo1 - mg1);
            float inv0 = 1.0f / (l0 * s0 + lo0 * t0);
            float inv1 = 1.0f / (l1 * s1 + lo1 * t1);
            const float* cb = Cs + (wb + p4) * 132 + 2 * q4;
            float* orow0 = out + ((size_t)(b * S + q0 + wb + p4)) * 64 + 2 * q4;
            float* orow1 = orow0 + 8 * 64;
#pragma unroll
            for (int j2 = 0; j2 < 8; j2++) {
                float2 c0 = *(const float2*)(cb + j2 * 8);
                float2 c1 = *(const float2*)(cb + 8 * 132 + j2 * 8);
                *(float2*)(orow0 + j2 * 8) =
                    make_float2((of[j2][0] * s0 + c0.x * t0) * inv0,
                                (of[j2][1] * s0 + c0.y * t0) * inv0);
                *(float2*)(orow1 + j2 * 8) =
                    make_float2((of[j2][2] * s1 + c1.x * t1) * inv1,
                                (of[j2][3] * s1 + c1.y * t1) * inv1);
            }
        }
        __syncthreads();                       // Cs/Xm/Xl/s_unit free for next unit
    }
}

// ---------------------------------------------------------------------------
extern "C" void kernel_launch(void* const* d_in, const int* in_sizes, int n_in,
                              void* d_out, int out_size)
{
    const float* x  = (const float*)d_in[0];
    const float* wq = (const float*)d_in[1];
    const float* wk = (const float*)d_in[2];
    const float* wv = (const float*)d_in[3];
    float* out = (float*)d_out;

    cudaFuncSetAttribute(proj_kernel,
                         cudaFuncAttributeMaxDynamicSharedMemorySize, PROJ_SMEM);
    cudaFuncSetAttribute(attn_kernel,
                         cudaFuncAttributeMaxDynamicSharedMemorySize, ATTN_SMEM);

    proj_kernel<<<M / 256, 512, PROJ_SMEM>>>(x, wq, wk, wv);
    attn_kernel<<<148, 512, ATTN_SMEM>>>(out);
}

// round 14
// speedup vs baseline: 1.1248x; 1.0674x over previous
#include <cuda_runtime.h>
#include <cstdint>

// ---------------------------------------------------------------------------
// AttentionHead  B=8 S=4096 D=1024 DK=64
// Round 14: attn = R10 verbatim (128 causal-paired blocks; stealing capped by
// longest-tile bound and reverted). proj = R10 skeleton + W pre-rounded once
// to tf32-exact g_Wr (isolated change; removes 75% of hot-loop CVTs).
// ---------------------------------------------------------------------------

constexpr int B  = 8;
constexpr int S  = 4096;
constexpr int D  = 1024;
constexpr int DK = 64;
constexpr int M  = B * S;

__device__ float g_Q[M * DK];
__device__ float g_K[M * DK];
__device__ float g_V[M * DK];    // used as [B][64][4096], t pair-permuted
__device__ float g_Wr[192 * D];  // tf32-exact [wQ|wK|wV], row-major [192][1024]

__device__ __forceinline__ float ex2f(float x) {
    float y; asm("ex2.approx.ftz.f32 %0, %1;" : "=f"(y) : "f"(x)); return y;
}
__device__ __forceinline__ uint32_t tf32_rna(float f) {
    uint32_t u; asm("cvt.rna.tf32.f32 %0, %1;" : "=r"(u) : "f"(f)); return u;
}
__device__ __forceinline__ float tf32ef(float f) {
    return __uint_as_float(tf32_rna(f));
}
__device__ __forceinline__ uint32_t f2u(float f) { return __float_as_uint(f); }

__host__ __device__ __forceinline__ int perm8(int u) {
    return 2 * (u & 3) + ((u >> 2) & 1);
}

__device__ __forceinline__ void cpa16(void* dst_smem, const void* src) {
    uint32_t a;
    asm("{ .reg .u64 t; cvta.to.shared.u64 t, %1; cvt.u32.u64 %0, t; }"
        : "=r"(a) : "l"(dst_smem));
    asm volatile("cp.async.cg.shared.global [%0], [%1], 16;" :: "r"(a), "l"(src));
}
#define CPA_COMMIT() asm volatile("cp.async.commit_group;" ::: "memory")
template <int N>
__device__ __forceinline__ void cpa_wait() {
    asm volatile("cp.async.wait_group %0;" :: "n"(N) : "memory");
}
#define BAR_SYNC(id) asm volatile("bar.sync %0, 256;" :: "r"(id) : "memory")

__device__ __forceinline__ void mma8(float c[4], const uint32_t a[4],
                                     uint32_t b0, uint32_t b1) {
    asm volatile(
        "mma.sync.aligned.m16n8k8.row.col.f32.tf32.tf32.f32 "
        "{%0,%1,%2,%3}, {%4,%5,%6,%7}, {%8,%9}, {%0,%1,%2,%3};"
        : "+f"(c[0]), "+f"(c[1]), "+f"(c[2]), "+f"(c[3])
        : "r"(a[0]), "r"(a[1]), "r"(a[2]), "r"(a[3]), "r"(b0), "r"(b1));
}

constexpr float NEG = -1e30f;

// ---------------------------------------------------------------------------
// Phase 0: round W once to tf32-exact fp32 (192x1024 elems)
// ---------------------------------------------------------------------------
__global__ void w_round_kernel(const float* __restrict__ wq,
                               const float* __restrict__ wk,
                               const float* __restrict__ wv)
{
    int i = blockIdx.x * 256 + threadIdx.x;     // 768 x 256 = 196608
    int n = i >> 10;
    const float* w = (n < 64) ? wq : (n < 128) ? wk : wv;
    g_Wr[i] = tf32ef(w[(size_t)(n & 63) * D + (i & 1023)]);
}

// ---------------------------------------------------------------------------
// Phase 1: C[M,192] = X[M,1024] @ Wr^T   (R10 skeleton: stride 36,
// scalar LDS, A-side per-use CVT; B-side raw bits from tf32-exact g_Wr)
// ---------------------------------------------------------------------------
constexpr int PXS = 256 * 36;
constexpr int PWS = 192 * 36;
constexpr int PSTG = PXS + PWS;
constexpr int PROJ_SMEM = 2 * PSTG * 4;       // 129024 B

__global__ __launch_bounds__(512, 1)
void proj_kernel(const float* __restrict__ x)
{
    extern __shared__ float ps[];
    const int tid  = threadIdx.x;
    const int lane = tid & 31;
    const int warp = tid >> 5;
    const int wm   = warp & 7;
    const int wn   = warp >> 3;
    const int m0   = blockIdx.x * 256;

    auto load_stage = [&](int st, int k0) {
        float* xs = ps + st * PSTG;
        float* ws = xs + PXS;
#pragma unroll
        for (int p = 0; p < 4; p++) {
            int c = tid + p * 512;
            int t = c >> 3, seg = c & 7;
            cpa16(xs + t * 36 + seg * 4, x + (size_t)(m0 + t) * D + k0 + seg * 4);
        }
#pragma unroll
        for (int p = 0; p < 3; p++) {
            int c = tid + p * 512;
            int n = c >> 3, seg = c & 7;
            cpa16(ws + n * 36 + seg * 4, g_Wr + (size_t)n * D + k0 + seg * 4);
        }
        CPA_COMMIT();
    };

    float acc[2][12][4];
#pragma unroll
    for (int mt = 0; mt < 2; mt++)
#pragma unroll
        for (int nt = 0; nt < 12; nt++)
#pragma unroll
            for (int e = 0; e < 4; e++) acc[mt][nt][e] = 0.0f;

    load_stage(0, 0);

    for (int it = 0; it < 32; ++it) {
        cpa_wait<0>();
        __syncthreads();
        if (it + 1 < 32) load_stage((it + 1) & 1, (it + 1) * 32);

        const float* xs = ps + (it & 1) * PSTG;
        const float* ws = xs + PXS;
        const float* aB = xs + (wm * 32 + (lane >> 2)) * 36 + (lane & 3);
        const float* bB = ws + (wn * 96 + (lane >> 2)) * 36 + (lane & 3);

#pragma unroll
        for (int s = 0; s < 4; s++) {
            uint32_t a[2][4];
#pragma unroll
            for (int mt = 0; mt < 2; mt++) {
                const float* ap = aB + mt * 16 * 36 + s * 8;
                a[mt][0] = tf32_rna(ap[0]);
                a[mt][1] = tf32_rna(ap[8 * 36]);
                a[mt][2] = tf32_rna(ap[4]);
                a[mt][3] = tf32_rna(ap[8 * 36 + 4]);
            }
#pragma unroll
            for (int nt = 0; nt < 12; nt++) {
                const float* bp = bB + nt * 8 * 36 + s * 8;
                uint32_t b0 = f2u(bp[0]);     // already tf32-exact
                uint32_t b1 = f2u(bp[4]);
                mma8(acc[0][nt], a[0], b0, b1);
                mma8(acc[1][nt], a[1], b0, b1);
            }
        }
    }

    // epilogue: Q scaled; all outputs tf32-exact; permuted scratch layouts.
    const float SC = (float)(1.4426950408889634 / 32.0);
#pragma unroll
    for (int mt = 0; mt < 2; mt++) {
#pragma unroll
        for (int nt = 0; nt < 12; nt++) {
            int col = wn * 96 + nt * 8 + 2 * (lane & 3);
            int row = m0 + wm * 32 + mt * 16 + (lane >> 2);
            if (col < 128) {
                float* outp = (col < 64) ? g_Q : g_K;
                float sc = (col < 64) ? SC : 1.0f;
                int b8  = (col & 63) & ~7;
                int p0  = b8 | perm8(col & 7);
                int p1  = b8 | perm8((col + 1) & 7);
                outp[(size_t)row * DK + p0]       = tf32ef(acc[mt][nt][0] * sc);
                outp[(size_t)row * DK + p1]       = tf32ef(acc[mt][nt][1] * sc);
                outp[(size_t)(row + 8) * DK + p0] = tf32ef(acc[mt][nt][2] * sc);
                outp[(size_t)(row + 8) * DK + p1] = tf32ef(acc[mt][nt][3] * sc);
            } else {
                int lc = col & 63;
                int b0r = row >> 12,  s0 = row & 4095;
                int b1r = (row + 8) >> 12, s1 = (row + 8) & 4095;
                size_t pt0 = (size_t)(s0 & ~7) | perm8(s0 & 7);
                size_t pt1 = (size_t)(s1 & ~7) | perm8(s1 & 7);
                g_V[((size_t)b0r * 64 + lc)     * 4096 + pt0] = tf32ef(acc[mt][nt][0]);
                g_V[((size_t)b0r * 64 + lc + 1) * 4096 + pt0] = tf32ef(acc[mt][nt][1]);
                g_V[((size_t)b1r * 64 + lc)     * 4096 + pt1] = tf32ef(acc[mt][nt][2]);
                g_V[((size_t)b1r * 64 + lc + 1) * 4096 + pt1] = tf32ef(acc[mt][nt][3]);
            }
        }
    }
}

// ---------------------------------------------------------------------------
// Phase 2: flash attention (R10 verbatim): 128 causal-paired blocks,
// de-lockstepped halves (named barriers), register-resident P,
// exact diag-quarter skip, per-q-tile LSE merge.
// ---------------------------------------------------------------------------
constexpr int KSZ  = 128 * 72;
constexpr int VTSZ = 64 * 136;
constexpr int STG  = KSZ + VTSZ;
constexpr int COFF = 2 * STG;
constexpr int CSZ  = 128 * 132;
constexpr int ATTN_SMEM = (COFF + CSZ) * 4;   // 210944 B

__global__ __launch_bounds__(512, 1)
void attn_kernel(float* __restrict__ out)
{
    extern __shared__ float sm[];
    __shared__ float Xm[128];
    __shared__ float Xl[128];

    const int b    = blockIdx.y;
    const int pj   = blockIdx.x;
    const int tid  = threadIdx.x;
    const int lane = tid & 31;
    const int warp = tid >> 5;
    const int wc   = warp >> 3;
    const int wr   = warp & 7;
    const int wb   = wr * 16;
    const int kb   = wc * 64;
    const int p4   = lane >> 2;
    const int q4   = lane & 3;
    const int htid = tid & 255;
    const int barid = 1 + wc;

    float* Cs = sm + COFF;

    auto load_kv = [&](int kt, int st) {
        float* Ks  = sm + st * STG;
        float* VTs = Ks + KSZ;
        const int t0 = kt * 128;
#pragma unroll
        for (int p = 0; p < 4; p++) {
            int c = htid + p * 256;
            int tl = c >> 4, seg = c & 15;
            int slot = kb + ((tl & ~7) | perm8(tl & 7));
            cpa16(Ks + slot * 72 + seg * 4,
                  g_K + ((size_t)(b * S + t0 + kb + tl)) * 64 + seg * 4);
        }
#pragma unroll
        for (int p = 0; p < 4; p++) {
            int c = htid + p * 256;
            int dk = c >> 4, ch = c & 15;
            cpa16(VTs + dk * 136 + kb + ch * 4,
                  g_V + ((size_t)b * 64 + dk) * 4096 + t0 + kb + ch * 4);
        }
        CPA_COMMIT();
    };

    for (int qsel = 0; qsel < 2; qsel++) {
        const int qt = qsel ? (31 - pj) : pj;
        const int q0 = qt * 128;
        const int nt = qt + 1;

        load_kv(0, 0);

        uint32_t qa[8][4];
#pragma unroll
        for (int s = 0; s < 8; s++) {
            const float* qp = g_Q + ((size_t)(b * S + q0 + wb + p4)) * 64 + s * 8 + 2 * q4;
            float2 lo = *(const float2*)qp;
            float2 hi = *(const float2*)(qp + 8 * 64);
            qa[s][0] = f2u(lo.x);
            qa[s][1] = f2u(hi.x);
            qa[s][2] = f2u(lo.y);
            qa[s][3] = f2u(hi.y);
        }

        float of[8][4];
        float m0r = NEG, m1r = NEG, l0 = 0.0f, l1 = 0.0f;
#pragma unroll
        for (int j = 0; j < 8; j++)
#pragma unroll
            for (int e = 0; e < 4; e++) of[j][e] = 0.0f;

        for (int it = 0; it < nt; ++it) {
            const int st = it & 1;
            cpa_wait<0>();
            BAR_SYNC(barid);
            if (it + 1 < nt) load_kv(it + 1, st ^ 1);

            if (it == qt && kb > wb + 15) continue;   // fully-masked quarter

            const float* Ks  = sm + st * STG;
            const float* VTs = Ks + KSZ;

            float sf[8][4];
#pragma unroll
            for (int j = 0; j < 8; j++)
#pragma unroll
                for (int e = 0; e < 4; e++) sf[j][e] = 0.0f;

            const float* kB = Ks + (kb + p4) * 72 + 2 * q4;
#pragma unroll
            for (int s = 0; s < 8; s++) {
                const float* kp = kB + s * 8;
#pragma unroll
                for (int j = 0; j < 8; j++) {
                    float2 kv2 = *(const float2*)(kp + j * 8 * 72);
                    mma8(sf[j], qa[s], f2u(kv2.x), f2u(kv2.y));
                }
            }

            if (it == qt) {
                int r0 = wb + p4;
#pragma unroll
                for (int j = 0; j < 8; j++) {
                    int ta = kb + j * 8 + q4;
                    int tb = ta + 4;
                    if (ta > r0)     sf[j][0] = NEG;
                    if (tb > r0)     sf[j][1] = NEG;
                    if (ta > r0 + 8) sf[j][2] = NEG;
                    if (tb > r0 + 8) sf[j][3] = NEG;
                }
            }

            float mx0 = NEG, mx1 = NEG;
#pragma unroll
            for (int j = 0; j < 8; j++) {
                mx0 = fmaxf(mx0, fmaxf(sf[j][0], sf[j][1]));
                mx1 = fmaxf(mx1, fmaxf(sf[j][2], sf[j][3]));
            }
            mx0 = fmaxf(mx0, __shfl_xor_sync(0xffffffffu, mx0, 1));
            mx0 = fmaxf(mx0, __shfl_xor_sync(0xffffffffu, mx0, 2));
            mx1 = fmaxf(mx1, __shfl_xor_sync(0xffffffffu, mx1, 1));
            mx1 = fmaxf(mx1, __shfl_xor_sync(0xffffffffu, mx1, 2));
            float mn0 = fmaxf(m0r, mx0), mn1 = fmaxf(m1r, mx1);
            float al0 = ex2f(m0r - mn0), al1 = ex2f(m1r - mn1);
            float keep0 = (mn0 > -1e29f) ? 1.0f : 0.0f;
            float keep1 = (mn1 > -1e29f) ? 1.0f : 0.0f;
            m0r = mn0; m1r = mn1;
#pragma unroll
            for (int j = 0; j < 8; j++) {
                of[j][0] *= al0; of[j][1] *= al0;
                of[j][2] *= al1; of[j][3] *= al1;
            }

            float rs0 = 0.0f, rs1 = 0.0f;
            const float* vB = VTs + p4 * 136 + kb + 2 * q4;
#pragma unroll
            for (int s2 = 0; s2 < 8; s2++) {
                float p00 = tf32ef(ex2f(sf[s2][0] - mn0)) * keep0;
                float p01 = tf32ef(ex2f(sf[s2][1] - mn0)) * keep0;
                float p10 = tf32ef(ex2f(sf[s2][2] - mn1)) * keep1;
                float p11 = tf32ef(ex2f(sf[s2][3] - mn1)) * keep1;
                rs0 += p00 + p01;
                rs1 += p10 + p11;
                uint32_t pa[4];
                pa[0] = f2u(p00); pa[1] = f2u(p10);
                pa[2] = f2u(p01); pa[3] = f2u(p11);
                const float* vp = vB + s2 * 8;
#pragma unroll
                for (int j2 = 0; j2 < 8; j2++) {
                    float2 vv = *(const float2*)(vp + j2 * 8 * 136);
                    mma8(of[j2], pa, f2u(vv.x), f2u(vv.y));
                }
            }
            rs0 += __shfl_xor_sync(0xffffffffu, rs0, 1);
            rs0 += __shfl_xor_sync(0xffffffffu, rs0, 2);
            rs1 += __shfl_xor_sync(0xffffffffu, rs1, 1);
            rs1 += __shfl_xor_sync(0xffffffffu, rs1, 2);
            l0 = l0 * al0 + rs0;
            l1 = l1 * al1 + rs1;
        }

        __syncthreads();
        if (wc == 1) {
            float* cb = Cs + (wb + p4) * 132 + 2 * q4;
#pragma unroll
            for (int j2 = 0; j2 < 8; j2++) {
                *(float2*)(cb + j2 * 8)           = make_float2(of[j2][0], of[j2][1]);
                *(float2*)(cb + 8 * 132 + j2 * 8) = make_float2(of[j2][2], of[j2][3]);
            }
            if (q4 == 0) {
                Xm[wb + p4]     = m0r;  Xl[wb + p4]     = l0;
                Xm[wb + p4 + 8] = m1r;  Xl[wb + p4 + 8] = l1;
            }
        }
        __syncthreads();
        if (wc == 0) {
            float mo0 = Xm[wb + p4],     lo0 = Xl[wb + p4];
            float mo1 = Xm[wb + p4 + 8], lo1 = Xl[wb + p4 + 8];
            float mg0 = fmaxf(m0r, mo0), mg1 = fmaxf(m1r, mo1);
            float s0 = ex2f(m0r - mg0), t0 = ex2f(mo0 - mg0);
            float s1 = ex2f(m1r - mg1), t1 = ex2f(mo1 - mg1);
            float inv0 = 1.0f / (l0 * s0 + lo0 * t0);
            float inv1 = 1.0f / (l1 * s1 + lo1 * t1);
            const float* cb = Cs + (wb + p4) * 132 + 2 * q4;
            float* orow0 = out + ((size_t)(b * S + q0 + wb + p4)) * 64 + 2 * q4;
            float* orow1 = orow0 + 8 * 64;
#pragma unroll
            for (int j2 = 0; j2 < 8; j2++) {
                float2 c0 = *(const float2*)(cb + j2 * 8);
                float2 c1 = *(const float2*)(cb + 8 * 132 + j2 * 8);
                *(float2*)(orow0 + j2 * 8) =
                    make_float2((of[j2][0] * s0 + c0.x * t0) * inv0,
                                (of[j2][1] * s0 + c0.y * t0) * inv0);
                *(float2*)(orow1 + j2 * 8) =
                    make_float2((of[j2][2] * s1 + c1.x * t1) * inv1,
                                (of[j2][3] * s1 + c1.y * t1) * inv1);
            }
        }
        __syncthreads();
    }
}

// ---------------------------------------------------------------------------
extern "C" void kernel_launch(void* const* d_in, const int* in_sizes, int n_in,
                              void* d_out, int out_size)
{
    const float* x  = (const float*)d_in[0];
    const float* wq = (const float*)d_in[1];
    const float* wk = (const float*)d_in[2];
    const float* wv = (const float*)d_in[3];
    float* out = (float*)d_out;

    cudaFuncSetAttribute(proj_kernel,
                         cudaFuncAttributeMaxDynamicSharedMemorySize, PROJ_SMEM);
    cudaFuncSetAttribute(attn_kernel,
                         cudaFuncAttributeMaxDynamicSharedMemorySize, ATTN_SMEM);

    w_round_kernel<<<768, 256>>>(wq, wk, wv);
    proj_kernel<<<M / 256, 512, PROJ_SMEM>>>(x);
    attn_kernel<<<dim3(16, B), 512, ATTN_SMEM>>>(out);
}

// round 15
// speedup vs baseline: 1.1533x; 1.0253x over previous
#include <cuda_runtime.h>
#include <cstdint>

// ---------------------------------------------------------------------------
// AttentionHead  B=8 S=4096 D=1024 DK=64
// Round 15: R14 polish. (a) attn: keep-guards deleted (proven always-1 on
// processed tiles; skipped quarters handled by LSE merge). (b) w_round
// vectorized float4. proj/attn structure = R14 (best: 219.4 us).
// ---------------------------------------------------------------------------

constexpr int B  = 8;
constexpr int S  = 4096;
constexpr int D  = 1024;
constexpr int DK = 64;
constexpr int M  = B * S;

__device__ float g_Q[M * DK];
__device__ float g_K[M * DK];
__device__ float g_V[M * DK];    // used as [B][64][4096], t pair-permuted
__device__ float g_Wr[192 * D];  // tf32-exact [wQ|wK|wV], row-major [192][1024]

__device__ __forceinline__ float ex2f(float x) {
    float y; asm("ex2.approx.ftz.f32 %0, %1;" : "=f"(y) : "f"(x)); return y;
}
__device__ __forceinline__ uint32_t tf32_rna(float f) {
    uint32_t u; asm("cvt.rna.tf32.f32 %0, %1;" : "=r"(u) : "f"(f)); return u;
}
__device__ __forceinline__ float tf32ef(float f) {
    return __uint_as_float(tf32_rna(f));
}
__device__ __forceinline__ uint32_t f2u(float f) { return __float_as_uint(f); }

__host__ __device__ __forceinline__ int perm8(int u) {
    return 2 * (u & 3) + ((u >> 2) & 1);
}

__device__ __forceinline__ void cpa16(void* dst_smem, const void* src) {
    uint32_t a;
    asm("{ .reg .u64 t; cvta.to.shared.u64 t, %1; cvt.u32.u64 %0, t; }"
        : "=r"(a) : "l"(dst_smem));
    asm volatile("cp.async.cg.shared.global [%0], [%1], 16;" :: "r"(a), "l"(src));
}
#define CPA_COMMIT() asm volatile("cp.async.commit_group;" ::: "memory")
template <int N>
__device__ __forceinline__ void cpa_wait() {
    asm volatile("cp.async.wait_group %0;" :: "n"(N) : "memory");
}
#define BAR_SYNC(id) asm volatile("bar.sync %0, 256;" :: "r"(id) : "memory")

__device__ __forceinline__ void mma8(float c[4], const uint32_t a[4],
                                     uint32_t b0, uint32_t b1) {
    asm volatile(
        "mma.sync.aligned.m16n8k8.row.col.f32.tf32.tf32.f32 "
        "{%0,%1,%2,%3}, {%4,%5,%6,%7}, {%8,%9}, {%0,%1,%2,%3};"
        : "+f"(c[0]), "+f"(c[1]), "+f"(c[2]), "+f"(c[3])
        : "r"(a[0]), "r"(a[1]), "r"(a[2]), "r"(a[3]), "r"(b0), "r"(b1));
}

constexpr float NEG = -1e30f;

// ---------------------------------------------------------------------------
// Phase 0: round W once to tf32-exact fp32 (192x1024 elems, float4 per thread)
// ---------------------------------------------------------------------------
__global__ void w_round_kernel(const float* __restrict__ wq,
                               const float* __restrict__ wk,
                               const float* __restrict__ wv)
{
    int base = (blockIdx.x * 256 + threadIdx.x) * 4;   // 192 blocks x 256 x 4
    int n = base >> 10;
    const float* w = (n < 64) ? wq : (n < 128) ? wk : wv;
    float4 v = *(const float4*)(w + (size_t)(n & 63) * D + (base & 1023));
    *(float4*)(g_Wr + base) = make_float4(tf32ef(v.x), tf32ef(v.y),
                                          tf32ef(v.z), tf32ef(v.w));
}

// ---------------------------------------------------------------------------
// Phase 1: C[M,192] = X[M,1024] @ Wr^T   (R14 verbatim)
// ---------------------------------------------------------------------------
constexpr int PXS = 256 * 36;
constexpr int PWS = 192 * 36;
constexpr int PSTG = PXS + PWS;
constexpr int PROJ_SMEM = 2 * PSTG * 4;       // 129024 B

__global__ __launch_bounds__(512, 1)
void proj_kernel(const float* __restrict__ x)
{
    extern __shared__ float ps[];
    const int tid  = threadIdx.x;
    const int lane = tid & 31;
    const int warp = tid >> 5;
    const int wm   = warp & 7;
    const int wn   = warp >> 3;
    const int m0   = blockIdx.x * 256;

    auto load_stage = [&](int st, int k0) {
        float* xs = ps + st * PSTG;
        float* ws = xs + PXS;
#pragma unroll
        for (int p = 0; p < 4; p++) {
            int c = tid + p * 512;
            int t = c >> 3, seg = c & 7;
            cpa16(xs + t * 36 + seg * 4, x + (size_t)(m0 + t) * D + k0 + seg * 4);
        }
#pragma unroll
        for (int p = 0; p < 3; p++) {
            int c = tid + p * 512;
            int n = c >> 3, seg = c & 7;
            cpa16(ws + n * 36 + seg * 4, g_Wr + (size_t)n * D + k0 + seg * 4);
        }
        CPA_COMMIT();
    };

    float acc[2][12][4];
#pragma unroll
    for (int mt = 0; mt < 2; mt++)
#pragma unroll
        for (int nt = 0; nt < 12; nt++)
#pragma unroll
            for (int e = 0; e < 4; e++) acc[mt][nt][e] = 0.0f;

    load_stage(0, 0);

    for (int it = 0; it < 32; ++it) {
        cpa_wait<0>();
        __syncthreads();
        if (it + 1 < 32) load_stage((it + 1) & 1, (it + 1) * 32);

        const float* xs = ps + (it & 1) * PSTG;
        const float* ws = xs + PXS;
        const float* aB = xs + (wm * 32 + (lane >> 2)) * 36 + (lane & 3);
        const float* bB = ws + (wn * 96 + (lane >> 2)) * 36 + (lane & 3);

#pragma unroll
        for (int s = 0; s < 4; s++) {
            uint32_t a[2][4];
#pragma unroll
            for (int mt = 0; mt < 2; mt++) {
                const float* ap = aB + mt * 16 * 36 + s * 8;
                a[mt][0] = tf32_rna(ap[0]);
                a[mt][1] = tf32_rna(ap[8 * 36]);
                a[mt][2] = tf32_rna(ap[4]);
                a[mt][3] = tf32_rna(ap[8 * 36 + 4]);
            }
#pragma unroll
            for (int nt = 0; nt < 12; nt++) {
                const float* bp = bB + nt * 8 * 36 + s * 8;
                uint32_t b0 = f2u(bp[0]);     // already tf32-exact
                uint32_t b1 = f2u(bp[4]);
                mma8(acc[0][nt], a[0], b0, b1);
                mma8(acc[1][nt], a[1], b0, b1);
            }
        }
    }

    const float SC = (float)(1.4426950408889634 / 32.0);
#pragma unroll
    for (int mt = 0; mt < 2; mt++) {
#pragma unroll
        for (int nt = 0; nt < 12; nt++) {
            int col = wn * 96 + nt * 8 + 2 * (lane & 3);
            int row = m0 + wm * 32 + mt * 16 + (lane >> 2);
            if (col < 128) {
                float* outp = (col < 64) ? g_Q : g_K;
                float sc = (col < 64) ? SC : 1.0f;
                int b8  = (col & 63) & ~7;
                int p0  = b8 | perm8(col & 7);
                int p1  = b8 | perm8((col + 1) & 7);
                outp[(size_t)row * DK + p0]       = tf32ef(acc[mt][nt][0] * sc);
                outp[(size_t)row * DK + p1]       = tf32ef(acc[mt][nt][1] * sc);
                outp[(size_t)(row + 8) * DK + p0] = tf32ef(acc[mt][nt][2] * sc);
                outp[(size_t)(row + 8) * DK + p1] = tf32ef(acc[mt][nt][3] * sc);
            } else {
                int lc = col & 63;
                int b0r = row >> 12,  s0 = row & 4095;
                int b1r = (row + 8) >> 12, s1 = (row + 8) & 4095;
                size_t pt0 = (size_t)(s0 & ~7) | perm8(s0 & 7);
                size_t pt1 = (size_t)(s1 & ~7) | perm8(s1 & 7);
                g_V[((size_t)b0r * 64 + lc)     * 4096 + pt0] = tf32ef(acc[mt][nt][0]);
                g_V[((size_t)b0r * 64 + lc + 1) * 4096 + pt0] = tf32ef(acc[mt][nt][1]);
                g_V[((size_t)b1r * 64 + lc)     * 4096 + pt1] = tf32ef(acc[mt][nt][2]);
                g_V[((size_t)b1r * 64 + lc + 1) * 4096 + pt1] = tf32ef(acc[mt][nt][3]);
            }
        }
    }
}

// ---------------------------------------------------------------------------
// Phase 2: flash attention (R10/R14 structure; keep-guards removed).
// ---------------------------------------------------------------------------
constexpr int KSZ  = 128 * 72;
constexpr int VTSZ = 64 * 136;
constexpr int STG  = KSZ + VTSZ;
constexpr int COFF = 2 * STG;
constexpr int CSZ  = 128 * 132;
constexpr int ATTN_SMEM = (COFF + CSZ) * 4;   // 210944 B

__global__ __launch_bounds__(512, 1)
void attn_kernel(float* __restrict__ out)
{
    extern __shared__ float sm[];
    __shared__ float Xm[128];
    __shared__ float Xl[128];

    const int b    = blockIdx.y;
    const int pj   = blockIdx.x;
    const int tid  = threadIdx.x;
    const int lane = tid & 31;
    const int warp = tid >> 5;
    const int wc   = warp >> 3;
    const int wr   = warp & 7;
    const int wb   = wr * 16;
    const int kb   = wc * 64;
    const int p4   = lane >> 2;
    const int q4   = lane & 3;
    const int htid = tid & 255;
    const int barid = 1 + wc;

    float* Cs = sm + COFF;

    auto load_kv = [&](int kt, int st) {
        float* Ks  = sm + st * STG;
        float* VTs = Ks + KSZ;
        const int t0 = kt * 128;
#pragma unroll
        for (int p = 0; p < 4; p++) {
            int c = htid + p * 256;
            int tl = c >> 4, seg = c & 15;
            int slot = kb + ((tl & ~7) | perm8(tl & 7));
            cpa16(Ks + slot * 72 + seg * 4,
                  g_K + ((size_t)(b * S + t0 + kb + tl)) * 64 + seg * 4);
        }
#pragma unroll
        for (int p = 0; p < 4; p++) {
            int c = htid + p * 256;
            int dk = c >> 4, ch = c & 15;
            cpa16(VTs + dk * 136 + kb + ch * 4,
                  g_V + ((size_t)b * 64 + dk) * 4096 + t0 + kb + ch * 4);
        }
        CPA_COMMIT();
    };

    for (int qsel = 0; qsel < 2; qsel++) {
        const int qt = qsel ? (31 - pj) : pj;
        const int q0 = qt * 128;
        const int nt = qt + 1;

        load_kv(0, 0);

        uint32_t qa[8][4];
#pragma unroll
        for (int s = 0; s < 8; s++) {
            const float* qp = g_Q + ((size_t)(b * S + q0 + wb + p4)) * 64 + s * 8 + 2 * q4;
            float2 lo = *(const float2*)qp;
            float2 hi = *(const float2*)(qp + 8 * 64);
            qa[s][0] = f2u(lo.x);
            qa[s][1] = f2u(hi.x);
            qa[s][2] = f2u(lo.y);
            qa[s][3] = f2u(hi.y);
        }

        float of[8][4];
        float m0r = NEG, m1r = NEG, l0 = 0.0f, l1 = 0.0f;
#pragma unroll
        for (int j = 0; j < 8; j++)
#pragma unroll
            for (int e = 0; e < 4; e++) of[j][e] = 0.0f;

        for (int it = 0; it < nt; ++it) {
            const int st = it & 1;
            cpa_wait<0>();
            BAR_SYNC(barid);
            if (it + 1 < nt) load_kv(it + 1, st ^ 1);

            if (it == qt && kb > wb + 15) continue;   // fully-masked quarter

            const float* Ks  = sm + st * STG;
            const float* VTs = Ks + KSZ;

            float sf[8][4];
#pragma unroll
            for (int j = 0; j < 8; j++)
#pragma unroll
                for (int e = 0; e < 4; e++) sf[j][e] = 0.0f;

            const float* kB = Ks + (kb + p4) * 72 + 2 * q4;
#pragma unroll
            for (int s = 0; s < 8; s++) {
                const float* kp = kB + s * 8;
#pragma unroll
                for (int j = 0; j < 8; j++) {
                    float2 kv2 = *(const float2*)(kp + j * 8 * 72);
                    mma8(sf[j], qa[s], f2u(kv2.x), f2u(kv2.y));
                }
            }

            if (it == qt) {
                int r0 = wb + p4;
#pragma unroll
                for (int j = 0; j < 8; j++) {
                    int ta = kb + j * 8 + q4;
                    int tb = ta + 4;
                    if (ta > r0)     sf[j][0] = NEG;
                    if (tb > r0)     sf[j][1] = NEG;
                    if (ta > r0 + 8) sf[j][2] = NEG;
                    if (tb > r0 + 8) sf[j][3] = NEG;
                }
            }

            float mx0 = NEG, mx1 = NEG;
#pragma unroll
            for (int j = 0; j < 8; j++) {
                mx0 = fmaxf(mx0, fmaxf(sf[j][0], sf[j][1]));
                mx1 = fmaxf(mx1, fmaxf(sf[j][2], sf[j][3]));
            }
            mx0 = fmaxf(mx0, __shfl_xor_sync(0xffffffffu, mx0, 1));
            mx0 = fmaxf(mx0, __shfl_xor_sync(0xffffffffu, mx0, 2));
            mx1 = fmaxf(mx1, __shfl_xor_sync(0xffffffffu, mx1, 1));
            mx1 = fmaxf(mx1, __shfl_xor_sync(0xffffffffu, mx1, 2));
            // processed tiles always contain >=1 unmasked column per row
            // (kb <= wb+15 with 16-aligned wb forces wb >= kb), so mn is finite.
            float mn0 = fmaxf(m0r, mx0), mn1 = fmaxf(m1r, mx1);
            float al0 = ex2f(m0r - mn0), al1 = ex2f(m1r - mn1);
            m0r = mn0; m1r = mn1;
#pragma unroll
            for (int j = 0; j < 8; j++) {
                of[j][0] *= al0; of[j][1] *= al0;
                of[j][2] *= al1; of[j][3] *= al1;
            }

            float rs0 = 0.0f, rs1 = 0.0f;
            const float* vB = VTs + p4 * 136 + kb + 2 * q4;
#pragma unroll
            for (int s2 = 0; s2 < 8; s2++) {
                float p00 = tf32ef(ex2f(sf[s2][0] - mn0));
                float p01 = tf32ef(ex2f(sf[s2][1] - mn0));
                float p10 = tf32ef(ex2f(sf[s2][2] - mn1));
                float p11 = tf32ef(ex2f(sf[s2][3] - mn1));
                rs0 += p00 + p01;
                rs1 += p10 + p11;
                uint32_t pa[4];
                pa[0] = f2u(p00); pa[1] = f2u(p10);
                pa[2] = f2u(p01); pa[3] = f2u(p11);
                const float* vp = vB + s2 * 8;
#pragma unroll
                for (int j2 = 0; j2 < 8; j2++) {
                    float2 vv = *(const float2*)(vp + j2 * 8 * 136);
                    mma8(of[j2], pa, f2u(vv.x), f2u(vv.y));
                }
            }
            rs0 += __shfl_xor_sync(0xffffffffu, rs0, 1);
            rs0 += __shfl_xor_sync(0xffffffffu, rs0, 2);
            rs1 += __shfl_xor_sync(0xffffffffu, rs1, 1);
            rs1 += __shfl_xor_sync(0xffffffffu, rs1, 2);
            l0 = l0 * al0 + rs0;
            l1 = l1 * al1 + rs1;
        }

        __syncthreads();
        if (wc == 1) {
            float* cb = Cs + (wb + p4) * 132 + 2 * q4;
#pragma unroll
            for (int j2 = 0; j2 < 8; j2++) {
                *(float2*)(cb + j2 * 8)           = make_float2(of[j2][0], of[j2][1]);
                *(float2*)(cb + 8 * 132 + j2 * 8) = make_float2(of[j2][2], of[j2][3]);
            }
            if (q4 == 0) {
                Xm[wb + p4]     = m0r;  Xl[wb + p4]     = l0;
                Xm[wb + p4 + 8] = m1r;  Xl[wb + p4 + 8] = l1;
            }
        }
        __syncthreads();
        if (wc == 0) {
            float mo0 = Xm[wb + p4],     lo0 = Xl[wb + p4];
            float mo1 = Xm[wb + p4 + 8], lo1 = Xl[wb + p4 + 8];
            float mg0 = fmaxf(m0r, mo0), mg1 = fmaxf(m1r, mo1);
            float s0 = ex2f(m0r - mg0), t0 = ex2f(mo0 - mg0);
            float s1 = ex2f(m1r - mg1), t1 = ex2f(mo1 - mg1);
            float inv0 = 1.0f / (l0 * s0 + lo0 * t0);
            float inv1 = 1.0f / (l1 * s1 + lo1 * t1);
            const float* cb = Cs + (wb + p4) * 132 + 2 * q4;
            float* orow0 = out + ((size_t)(b * S + q0 + wb + p4)) * 64 + 2 * q4;
            float* orow1 = orow0 + 8 * 64;
#pragma unroll
            for (int j2 = 0; j2 < 8; j2++) {
                float2 c0 = *(const float2*)(cb + j2 * 8);
                float2 c1 = *(const float2*)(cb + 8 * 132 + j2 * 8);
                *(float2*)(orow0 + j2 * 8) =
                    make_float2((of[j2][0] * s0 + c0.x * t0) * inv0,
                                (of[j2][1] * s0 + c0.y * t0) * inv0);
                *(float2*)(orow1 + j2 * 8) =
                    make_float2((of[j2][2] * s1 + c1.x * t1) * inv1,
                                (of[j2][3] * s1 + c1.y * t1) * inv1);
            }
        }
        __syncthreads();
    }
}

// ---------------------------------------------------------------------------
extern "C" void kernel_launch(void* const* d_in, const int* in_sizes, int n_in,
                              void* d_out, int out_size)
{
    const float* x  = (const float*)d_in[0];
    const float* wq = (const float*)d_in[1];
    const float* wk = (const float*)d_in[2];
    const float* wv = (const float*)d_in[3];
    float* out = (float*)d_out;

    cudaFuncSetAttribute(proj_kernel,
                         cudaFuncAttributeMaxDynamicSharedMemorySize, PROJ_SMEM);
    cudaFuncSetAttribute(attn_kernel,
                         cudaFuncAttributeMaxDynamicSharedMemorySize, ATTN_SMEM);

    w_round_kernel<<<192, 256>>>(wq, wk, wv);
    proj_kernel<<<M / 256, 512, PROJ_SMEM>>>(x);
    attn_kernel<<<dim3(16, B), 512, ATTN_SMEM>>>(out);
}